// round 3
// baseline (speedup 1.0000x reference)
#include <cuda_runtime.h>
#include <math.h>

#define B_  4
#define T_  2048
#define D_  128
#define H_  8
#define BH_ (B_*H_)

// scratch (device globals -- no allocation allowed)
__device__ float g_q [BH_*T_*D_];
__device__ float g_k [BH_*T_*D_];
__device__ float g_v [BH_*T_*D_];
__device__ float g_ao[B_*T_*H_*D_];

#define NEGINF (-1e30f)

// ---------------------------------------------------------------------------
// Kernel 1: fused QKV projection.  X[8192,128] @ W[128,1024] for 3 weights.
// grid (16 ncols, 64 mrows, 3 matrices), 256 threads.
// Output layout: [b*H+h][t][d].  v scaled by 128^-0.25.
// ---------------------------------------------------------------------------
__global__ __launch_bounds__(256, 1)
void qkv_kernel(const float* __restrict__ x,  const float* __restrict__ Wq,
                const float* __restrict__ Wk, const float* __restrict__ Wv)
{
    extern __shared__ float sm[];
    float* Xs = sm;                 // [128][129]
    float* Ws = sm + 128*129;       // [128][68]

    const int bx = blockIdx.x, by = blockIdx.y, mat = blockIdx.z;
    const float* W   = (mat == 0) ? Wq : (mat == 1 ? Wk : Wv);
    float* outp      = (mat == 0) ? g_q : (mat == 1 ? g_k : g_v);
    const float vscale = (mat == 2) ? 0.29730177875068026f : 1.0f; // 128^-0.25
    const int tid = threadIdx.x;

    // load X tile [128 x 128], store with stride 129 (scalar STS, low conflict)
    const float* xg = x + (by * 128) * D_;
    #pragma unroll
    for (int r = 0; r < 16; ++r) {
        int lin = r * 256 + tid;
        int m = lin >> 5, c4 = lin & 31;
        float4 v4 = *(const float4*)(xg + m * D_ + c4 * 4);
        float* dst = Xs + m * 129 + c4 * 4;
        dst[0] = v4.x; dst[1] = v4.y; dst[2] = v4.z; dst[3] = v4.w;
    }
    // load W tile [128 x 64], stride 68 (float4 aligned)
    const float* wg = W + bx * 64;
    #pragma unroll
    for (int r = 0; r < 8; ++r) {
        int lin = r * 256 + tid;
        int c = lin >> 4, n4 = lin & 15;
        float4 v4 = *(const float4*)(wg + c * 1024 + n4 * 4);
        *(float4*)(Ws + c * 68 + n4 * 4) = v4;
    }
    __syncthreads();

    const int ty = tid >> 4, tx = tid & 15;   // 16x16, micro 8x4
    float acc[8][4];
    #pragma unroll
    for (int i = 0; i < 8; ++i)
        #pragma unroll
        for (int j = 0; j < 4; ++j) acc[i][j] = 0.f;

    #pragma unroll 8
    for (int kk = 0; kk < 128; ++kk) {
        float a[8];
        #pragma unroll
        for (int i = 0; i < 8; ++i) a[i] = Xs[(ty * 8 + i) * 129 + kk];
        float4 b4 = *(const float4*)(Ws + kk * 68 + tx * 4);
        float b[4] = {b4.x, b4.y, b4.z, b4.w};
        #pragma unroll
        for (int i = 0; i < 8; ++i)
            #pragma unroll
            for (int j = 0; j < 4; ++j) acc[i][j] += a[i] * b[j];
    }

    #pragma unroll
    for (int i = 0; i < 8; ++i) {
        int mg = by * 128 + ty * 8 + i;
        int b  = mg >> 11;                 // / 2048
        int t  = mg & (T_ - 1);
        int n  = bx * 64 + tx * 4;
        int h  = n >> 7;
        int d  = n & 127;
        float4 o4 = make_float4(acc[i][0] * vscale, acc[i][1] * vscale,
                                acc[i][2] * vscale, acc[i][3] * vscale);
        *(float4*)(outp + (((long long)(b * H_ + h) * T_ + t) * D_) + d) = o4;
    }
}

// ---------------------------------------------------------------------------
// Kernel 2: causal flash attention (fp32).
// grid (16 query tiles, 32 bh), 256 threads.  BM=128 queries, BN=64 keys.
// ---------------------------------------------------------------------------
__global__ __launch_bounds__(256, 1)
void attn_kernel()
{
    extern __shared__ float sm[];
    float* Qs = sm;                         // [128][129]
    float* Ks = Qs + 128 * 129;             // [ 64][129]
    float* Vs = Ks +  64 * 129;             // [ 64][132]
    float* Ps = Vs +  64 * 132;             // [128][ 65]

    const int bh    = blockIdx.y;
    const int qi    = (int)gridDim.x - 1 - (int)blockIdx.x;  // big tiles first
    const int qbase = qi * 128;
    const int tid   = threadIdx.x;
    const int ty    = tid >> 4, tx = tid & 15;   // 16x16 thread grid

    const float* qg = g_q + ((long long)bh * T_ + qbase) * D_;
    const float* kg = g_k + (long long)bh * T_ * D_;
    const float* vg = g_v + (long long)bh * T_ * D_;

    // load Q tile once
    #pragma unroll
    for (int r = 0; r < 16; ++r) {
        int lin = r * 256 + tid;
        int m = lin >> 5, c4 = lin & 31;
        float4 v4 = *(const float4*)(qg + m * D_ + c4 * 4);
        float* dst = Qs + m * 129 + c4 * 4;
        dst[0] = v4.x; dst[1] = v4.y; dst[2] = v4.z; dst[3] = v4.w;
    }

    float mrow[8], lrow[8], o[8][8];
    #pragma unroll
    for (int i = 0; i < 8; ++i) {
        mrow[i] = NEGINF; lrow[i] = 0.f;
        #pragma unroll
        for (int j = 0; j < 8; ++j) o[i][j] = 0.f;
    }

    const int   ntiles = 2 * qi + 2;
    const float sscale = 0.088388347648318447f;   // 128^-0.5

    for (int n = 0; n < ntiles; ++n) {
        __syncthreads();   // previous PV reads of Ks/Vs/Ps done
        // load K, V tiles (64 x 128)
        const float* kt = kg + (long long)n * 64 * D_;
        const float* vt = vg + (long long)n * 64 * D_;
        #pragma unroll
        for (int r = 0; r < 8; ++r) {
            int lin = r * 256 + tid;
            int m = lin >> 5, c4 = lin & 31;
            float4 k4 = *(const float4*)(kt + m * D_ + c4 * 4);
            float* dk = Ks + m * 129 + c4 * 4;
            dk[0] = k4.x; dk[1] = k4.y; dk[2] = k4.z; dk[3] = k4.w;
            float4 v4 = *(const float4*)(vt + m * D_ + c4 * 4);
            *(float4*)(Vs + m * 132 + c4 * 4) = v4;
        }
        __syncthreads();

        // S = Q K^T  (128x64 tile, 8x4 per thread)
        float s[8][4];
        #pragma unroll
        for (int i = 0; i < 8; ++i)
            #pragma unroll
            for (int j = 0; j < 4; ++j) s[i][j] = 0.f;

        #pragma unroll 8
        for (int kk = 0; kk < 128; ++kk) {
            float a[8], bb[4];
            #pragma unroll
            for (int i = 0; i < 8; ++i) a[i]  = Qs[(ty * 8 + i) * 129 + kk];
            #pragma unroll
            for (int j = 0; j < 4; ++j) bb[j] = Ks[(tx * 4 + j) * 129 + kk];
            #pragma unroll
            for (int i = 0; i < 8; ++i)
                #pragma unroll
                for (int j = 0; j < 4; ++j) s[i][j] += a[i] * bb[j];
        }

        // scale + causal mask
        #pragma unroll
        for (int i = 0; i < 8; ++i) {
            int rg = qbase + ty * 8 + i;
            #pragma unroll
            for (int j = 0; j < 4; ++j) {
                int cg = n * 64 + tx * 4 + j;
                s[i][j] = (cg <= rg) ? s[i][j] * sscale : NEGINF;
            }
        }

        // online softmax (row groups = 16 consecutive lanes)
        #pragma unroll
        for (int i = 0; i < 8; ++i) {
            float mx = fmaxf(fmaxf(s[i][0], s[i][1]), fmaxf(s[i][2], s[i][3]));
            #pragma unroll
            for (int off = 8; off >= 1; off >>= 1)
                mx = fmaxf(mx, __shfl_xor_sync(0xffffffffu, mx, off));
            float mnew  = fmaxf(mrow[i], mx);
            float alpha = __expf(mrow[i] - mnew);
            mrow[i] = mnew;
            float rs = 0.f;
            #pragma unroll
            for (int j = 0; j < 4; ++j) {
                float p = __expf(s[i][j] - mnew);
                s[i][j] = p; rs += p;
            }
            #pragma unroll
            for (int off = 8; off >= 1; off >>= 1)
                rs += __shfl_xor_sync(0xffffffffu, rs, off);
            lrow[i] = lrow[i] * alpha + rs;
            #pragma unroll
            for (int j = 0; j < 8; ++j) o[i][j] *= alpha;
            float* pp = Ps + (ty * 8 + i) * 65 + tx * 4;
            pp[0] = s[i][0]; pp[1] = s[i][1]; pp[2] = s[i][2]; pp[3] = s[i][3];
        }
        __syncthreads();

        // O += P @ V  (128x128, 8x8 per thread)
        #pragma unroll 8
        for (int kk = 0; kk < 64; ++kk) {
            float a[8];
            #pragma unroll
            for (int i = 0; i < 8; ++i) a[i] = Ps[(ty * 8 + i) * 65 + kk];
            float4 b0 = *(const float4*)(Vs + kk * 132 + tx * 8);
            float4 b1 = *(const float4*)(Vs + kk * 132 + tx * 8 + 4);
            float bb[8] = {b0.x, b0.y, b0.z, b0.w, b1.x, b1.y, b1.z, b1.w};
            #pragma unroll
            for (int i = 0; i < 8; ++i)
                #pragma unroll
                for (int j = 0; j < 8; ++j) o[i][j] += a[i] * bb[j];
        }
    }

    // epilogue: normalize and write [b][t][h*128+d]
    const int b = bh >> 3, h = bh & 7;
    #pragma unroll
    for (int i = 0; i < 8; ++i) {
        float inv = 1.f / lrow[i];
        int t = qbase + ty * 8 + i;
        float* og = g_ao + ((long long)(b * T_ + t)) * (H_ * D_) + h * D_ + tx * 8;
        float4 w0 = make_float4(o[i][0]*inv, o[i][1]*inv, o[i][2]*inv, o[i][3]*inv);
        float4 w1 = make_float4(o[i][4]*inv, o[i][5]*inv, o[i][6]*inv, o[i][7]*inv);
        *(float4*)(og)     = w0;
        *(float4*)(og + 4) = w1;
    }
}

// ---------------------------------------------------------------------------
// Kernel 3: output projection  AO[8192,1024] @ Wu[1024,128] + bu
// grid (128), 256 threads.  BM=64, BN=128, BK=32.
// ---------------------------------------------------------------------------
__global__ __launch_bounds__(256, 1)
void proj_kernel(const float* __restrict__ Wu, const float* __restrict__ bu,
                 float* __restrict__ out)
{
    __shared__ float As[64 * 33];    // [64][33]
    __shared__ float Bs[32 * 132];   // [32][132]

    const int by  = blockIdx.x;
    const int tid = threadIdx.x;
    const int ty  = tid >> 5, tx = tid & 31;   // 8 x 32, micro 8x4

    float acc[8][4];
    #pragma unroll
    for (int i = 0; i < 8; ++i)
        #pragma unroll
        for (int j = 0; j < 4; ++j) acc[i][j] = 0.f;

    for (int kc = 0; kc < 32; ++kc) {
        __syncthreads();
        // As: 64 x 32 from g_ao
        #pragma unroll
        for (int r = 0; r < 2; ++r) {
            int lin = r * 256 + tid;
            int m = lin >> 3, k4 = lin & 7;
            float4 v4 = *(const float4*)(g_ao + (long long)(by * 64 + m) * 1024
                                              + kc * 32 + k4 * 4);
            float* dst = As + m * 33 + k4 * 4;
            dst[0] = v4.x; dst[1] = v4.y; dst[2] = v4.z; dst[3] = v4.w;
        }
        // Bs: 32 x 128 from Wu
        #pragma unroll
        for (int r = 0; r < 4; ++r) {
            int lin = r * 256 + tid;
            int kk = lin >> 5, n4 = lin & 31;
            float4 v4 = *(const float4*)(Wu + (kc * 32 + kk) * 128 + n4 * 4);
            *(float4*)(Bs + kk * 132 + n4 * 4) = v4;
        }
        __syncthreads();

        #pragma unroll 8
        for (int kk = 0; kk < 32; ++kk) {
            float a[8];
            #pragma unroll
            for (int i = 0; i < 8; ++i) a[i] = As[(ty * 8 + i) * 33 + kk];
            float4 b4 = *(const float4*)(Bs + kk * 132 + tx * 4);
            float b[4] = {b4.x, b4.y, b4.z, b4.w};
            #pragma unroll
            for (int i = 0; i < 8; ++i)
                #pragma unroll
                for (int j = 0; j < 4; ++j) acc[i][j] += a[i] * b[j];
        }
    }

    float4 bias = *(const float4*)(bu + tx * 4);
    float bb[4] = {bias.x, bias.y, bias.z, bias.w};
    #pragma unroll
    for (int i = 0; i < 8; ++i) {
        int m = by * 64 + ty * 8 + i;
        float4 o4 = make_float4(acc[i][0] + bb[0], acc[i][1] + bb[1],
                                acc[i][2] + bb[2], acc[i][3] + bb[3]);
        *(float4*)(out + (long long)m * 128 + tx * 4) = o4;
    }
}

// ---------------------------------------------------------------------------
extern "C" void kernel_launch(void* const* d_in, const int* in_sizes, int n_in,
                              void* d_out, int out_size)
{
    const float* x  = (const float*)d_in[0];
    const float* Wq = (const float*)d_in[1];
    const float* Wk = (const float*)d_in[2];
    const float* Wv = (const float*)d_in[3];
    const float* Wu = (const float*)d_in[4];
    const float* bu = (const float*)d_in[5];
    float* out = (float*)d_out;

    const int SMEM1 = (128 * 129 + 128 * 68) * (int)sizeof(float);                // 100864
    const int SMEM2 = (128 * 129 + 64 * 129 + 64 * 132 + 128 * 65) * (int)sizeof(float); // 166144

    cudaFuncSetAttribute(qkv_kernel,  cudaFuncAttributeMaxDynamicSharedMemorySize, SMEM1);
    cudaFuncSetAttribute(attn_kernel, cudaFuncAttributeMaxDynamicSharedMemorySize, SMEM2);

    qkv_kernel<<<dim3(16, 64, 3), 256, SMEM1>>>(x, Wq, Wk, Wv);
    attn_kernel<<<dim3(16, 32), 256, SMEM2>>>();
    proj_kernel<<<dim3(128), 256>>>(Wu, bu, out);
}

// round 8
// speedup vs baseline: 2.7890x; 2.7890x over previous
#include <cuda_runtime.h>
#include <math.h>
#include <stdint.h>

#define B_  4
#define T_  2048
#define D_  128
#define H_  8
#define BH_ (B_*H_)
#define NEGINF (-1e30f)

// scratch (device globals -- no allocation allowed)
__device__ float g_q [BH_*T_*D_];
__device__ float g_k [BH_*T_*D_];
__device__ float g_v [BH_*T_*D_];
__device__ float g_ao[B_*T_*H_*D_];

__device__ __forceinline__ unsigned f2tf(float f){
    unsigned u; asm("cvt.rna.tf32.f32 %0, %1;" : "=r"(u) : "f"(f)); return u;
}

__device__ __forceinline__ void mma8(float4& d,
    unsigned a0, unsigned a1, unsigned a2, unsigned a3,
    unsigned b0, unsigned b1)
{
    asm volatile(
        "mma.sync.aligned.m16n8k8.row.col.f32.tf32.tf32.f32 "
        "{%0,%1,%2,%3},{%4,%5,%6,%7},{%8,%9},{%0,%1,%2,%3};"
        : "+f"(d.x), "+f"(d.y), "+f"(d.z), "+f"(d.w)
        : "r"(a0), "r"(a1), "r"(a2), "r"(a3), "r"(b0), "r"(b1));
}

// ---------------------------------------------------------------------------
// Kernel 1: fused QKV projection, tf32 MMA.
// X[8192,128] @ W[128,1024] x3.  grid (8 heads, 64 row tiles, 3 mats), 256 thr.
// Block tile 128x128, warp tile 32x64 (4x2 warps).
// ---------------------------------------------------------------------------
__global__ __launch_bounds__(256, 1)
void qkv_kernel(const float* __restrict__ x,  const float* __restrict__ Wq,
                const float* __restrict__ Wk, const float* __restrict__ Wv)
{
    extern __shared__ unsigned smu[];
    unsigned* Xs = smu;            // [128][68]
    unsigned* Ws = smu + 128*68;   // [64][132]

    const int bx = blockIdx.x;     // head (128-col tile)
    const int by = blockIdx.y;     // 128-row tile
    const int mat = blockIdx.z;
    const float* W = (mat == 0) ? Wq : (mat == 1 ? Wk : Wv);
    float* outp    = (mat == 0) ? g_q : (mat == 1 ? g_k : g_v);
    const float vs = (mat == 2) ? 0.29730177875068026f : 1.0f; // 128^-0.25

    const int tid = threadIdx.x;
    const int wid = tid >> 5, lane = tid & 31;
    const int g = lane >> 2, c = lane & 3;
    const int wm = wid >> 1, wn = wid & 1;

    float4 acc[2][8];
    #pragma unroll
    for (int i = 0; i < 2; ++i)
        #pragma unroll
        for (int j = 0; j < 8; ++j) acc[i][j] = make_float4(0.f, 0.f, 0.f, 0.f);

    for (int kc = 0; kc < 2; ++kc) {
        __syncthreads();
        // X tile: 128 rows x 64 k-cols  (tf32-converted)
        #pragma unroll
        for (int it = 0; it < 8; ++it) {
            int lin = it * 256 + tid;
            int m = lin >> 4, c4 = lin & 15;
            float4 v4 = *(const float4*)(x + (by*128 + m)*128 + kc*64 + c4*4);
            unsigned* d = Xs + m*68 + c4*4;
            d[0]=f2tf(v4.x); d[1]=f2tf(v4.y); d[2]=f2tf(v4.z); d[3]=f2tf(v4.w);
        }
        // W tile: 64 k-rows x 128 n-cols
        #pragma unroll
        for (int it = 0; it < 8; ++it) {
            int lin = it * 256 + tid;
            int k = lin >> 5, n4 = lin & 31;
            float4 v4 = *(const float4*)(W + (size_t)(kc*64 + k)*1024 + bx*128 + n4*4);
            unsigned* d = Ws + k*132 + n4*4;
            d[0]=f2tf(v4.x); d[1]=f2tf(v4.y); d[2]=f2tf(v4.z); d[3]=f2tf(v4.w);
        }
        __syncthreads();

        #pragma unroll
        for (int k8 = 0; k8 < 8; ++k8) {
            int kk = k8 * 8;
            unsigned a[2][4];
            #pragma unroll
            for (int mt = 0; mt < 2; ++mt) {
                int r = wm*32 + mt*16 + g;
                a[mt][0] = Xs[r*68 + kk + c];
                a[mt][1] = Xs[(r+8)*68 + kk + c];
                a[mt][2] = Xs[r*68 + kk + c + 4];
                a[mt][3] = Xs[(r+8)*68 + kk + c + 4];
            }
            #pragma unroll
            for (int nt = 0; nt < 8; ++nt) {
                unsigned b0 = Ws[(kk+c  )*132 + wn*64 + nt*8 + g];
                unsigned b1 = Ws[(kk+c+4)*132 + wn*64 + nt*8 + g];
                mma8(acc[0][nt], a[0][0], a[0][1], a[0][2], a[0][3], b0, b1);
                mma8(acc[1][nt], a[1][0], a[1][1], a[1][2], a[1][3], b0, b1);
            }
        }
    }

    // epilogue: out layout [b*H+h][t][d],  h == bx exactly (128-col tile)
    #pragma unroll
    for (int mt = 0; mt < 2; ++mt) {
        int mg0 = by*128 + wm*32 + mt*16 + g;
        int b0i = mg0 >> 11, t0 = mg0 & (T_ - 1);
        int mg1 = mg0 + 8;
        int b1i = mg1 >> 11, t1 = mg1 & (T_ - 1);
        #pragma unroll
        for (int nt = 0; nt < 8; ++nt) {
            int d = wn*64 + nt*8 + 2*c;
            float* p0 = outp + ((size_t)(b0i*H_ + bx)*T_ + t0)*D_ + d;
            *(float2*)p0 = make_float2(acc[mt][nt].x * vs, acc[mt][nt].y * vs);
            float* p1 = outp + ((size_t)(b1i*H_ + bx)*T_ + t1)*D_ + d;
            *(float2*)p1 = make_float2(acc[mt][nt].z * vs, acc[mt][nt].w * vs);
        }
    }
}

// ---------------------------------------------------------------------------
// Kernel 2: causal flash attention, tf32 MMA.
// grid (16 q-tiles, 32 bh), 256 threads.  BM=128 queries, BN=64 keys/step.
// S GEMM: 8x1 warp layout (warp owns 16 full rows -> in-warp softmax).
// PV GEMM: 4x2 warp layout; alpha / l cross layouts via 128-float smem.
// ---------------------------------------------------------------------------
__global__ __launch_bounds__(256, 1)
void attn_kernel()
{
    extern __shared__ unsigned smu[];
    unsigned* Qs = smu;                    // [128][132] tf32
    unsigned* Ks = Qs + 128*132;           // [ 64][132] tf32
    unsigned* Vs = Ks +  64*132;           // [ 64][132] tf32
    unsigned* Ps = Vs +  64*132;           // [128][ 68] tf32
    float*   red = (float*)(Ps + 128*68);  // [128] alpha, then l

    const int bh    = blockIdx.y;
    const int qi    = (int)gridDim.x - 1 - (int)blockIdx.x;  // big tiles first
    const int qbase = qi * 128;
    const int tid   = threadIdx.x;
    const int wid   = tid >> 5, lane = tid & 31;
    const int g = lane >> 2, c = lane & 3;
    const int wbase = wid * 16;              // S-layout row base
    const int wm2 = wid >> 1, wn2 = wid & 1; // PV layout

    const float* qg = g_q + ((size_t)bh * T_ + qbase) * D_;
    const float* kg = g_k + (size_t)bh * T_ * D_;
    const float* vg = g_v + (size_t)bh * T_ * D_;

    // load Q tile once (tf32)
    #pragma unroll
    for (int it = 0; it < 16; ++it) {
        int lin = it * 256 + tid;
        int m = lin >> 5, c4 = lin & 31;
        float4 v4 = *(const float4*)(qg + m*128 + c4*4);
        unsigned* d = Qs + m*132 + c4*4;
        d[0]=f2tf(v4.x); d[1]=f2tf(v4.y); d[2]=f2tf(v4.z); d[3]=f2tf(v4.w);
    }

    float m0 = NEGINF, m1 = NEGINF, l0 = 0.f, l1 = 0.f;
    float4 oacc[2][8];
    #pragma unroll
    for (int i = 0; i < 2; ++i)
        #pragma unroll
        for (int j = 0; j < 8; ++j) oacc[i][j] = make_float4(0.f, 0.f, 0.f, 0.f);

    const int   ntiles = 2 * qi + 2;
    const float sscale = 0.088388347648318447f;   // 128^-0.5

    for (int n = 0; n < ntiles; ++n) {
        __syncthreads();   // prior PV reads of Ks/Vs/Ps/red done
        const float* kt = kg + (size_t)n * 64 * D_;
        const float* vt = vg + (size_t)n * 64 * D_;
        #pragma unroll
        for (int it = 0; it < 8; ++it) {
            int lin = it * 256 + tid;
            int m = lin >> 5, c4 = lin & 31;
            float4 k4 = *(const float4*)(kt + m*128 + c4*4);
            unsigned* dk = Ks + m*132 + c4*4;
            dk[0]=f2tf(k4.x); dk[1]=f2tf(k4.y); dk[2]=f2tf(k4.z); dk[3]=f2tf(k4.w);
            float4 v4 = *(const float4*)(vt + m*128 + c4*4);
            unsigned* dv = Vs + m*132 + c4*4;
            dv[0]=f2tf(v4.x); dv[1]=f2tf(v4.y); dv[2]=f2tf(v4.z); dv[3]=f2tf(v4.w);
        }
        __syncthreads();

        // S = Q K^T : warp rows [wbase, wbase+16), all 64 cols
        float4 sacc[8];
        #pragma unroll
        for (int nt = 0; nt < 8; ++nt) sacc[nt] = make_float4(0.f, 0.f, 0.f, 0.f);

        #pragma unroll
        for (int k8 = 0; k8 < 16; ++k8) {
            int kk = k8 * 8;
            unsigned a0 = Qs[(wbase+g  )*132 + kk + c];
            unsigned a1 = Qs[(wbase+g+8)*132 + kk + c];
            unsigned a2 = Qs[(wbase+g  )*132 + kk + c + 4];
            unsigned a3 = Qs[(wbase+g+8)*132 + kk + c + 4];
            #pragma unroll
            for (int nt = 0; nt < 8; ++nt) {
                unsigned b0 = Ks[(nt*8+g)*132 + kk + c];
                unsigned b1 = Ks[(nt*8+g)*132 + kk + c + 4];
                mma8(sacc[nt], a0, a1, a2, a3, b0, b1);
            }
        }

        // scale
        #pragma unroll
        for (int nt = 0; nt < 8; ++nt) {
            sacc[nt].x *= sscale; sacc[nt].y *= sscale;
            sacc[nt].z *= sscale; sacc[nt].w *= sscale;
        }
        // causal mask (only last two tiles can touch the diagonal)
        if (n >= 2 * qi) {
            int rg0 = qbase + wbase + g, rg1 = rg0 + 8;
            #pragma unroll
            for (int nt = 0; nt < 8; ++nt) {
                int c0 = n*64 + nt*8 + 2*c;
                if (c0     > rg0) sacc[nt].x = NEGINF;
                if (c0 + 1 > rg0) sacc[nt].y = NEGINF;
                if (c0     > rg1) sacc[nt].z = NEGINF;
                if (c0 + 1 > rg1) sacc[nt].w = NEGINF;
            }
        }

        // online softmax: rows r0 = wbase+g, r1 = r0+8 (reduce over 4-lane group)
        float mx0 = NEGINF, mx1 = NEGINF;
        #pragma unroll
        for (int nt = 0; nt < 8; ++nt) {
            mx0 = fmaxf(mx0, fmaxf(sacc[nt].x, sacc[nt].y));
            mx1 = fmaxf(mx1, fmaxf(sacc[nt].z, sacc[nt].w));
        }
        mx0 = fmaxf(mx0, __shfl_xor_sync(0xffffffffu, mx0, 1));
        mx0 = fmaxf(mx0, __shfl_xor_sync(0xffffffffu, mx0, 2));
        mx1 = fmaxf(mx1, __shfl_xor_sync(0xffffffffu, mx1, 1));
        mx1 = fmaxf(mx1, __shfl_xor_sync(0xffffffffu, mx1, 2));

        float mn0 = fmaxf(m0, mx0), mn1 = fmaxf(m1, mx1);
        float al0 = __expf(m0 - mn0), al1 = __expf(m1 - mn1);
        m0 = mn0; m1 = mn1;

        int r0 = wbase + g, r1 = r0 + 8;
        float rs0 = 0.f, rs1 = 0.f;
        #pragma unroll
        for (int nt = 0; nt < 8; ++nt) {
            float px = __expf(sacc[nt].x - mn0);
            float py = __expf(sacc[nt].y - mn0);
            float pz = __expf(sacc[nt].z - mn1);
            float pw = __expf(sacc[nt].w - mn1);
            rs0 += px + py; rs1 += pz + pw;
            uint2 u0 = make_uint2(f2tf(px), f2tf(py));
            uint2 u1 = make_uint2(f2tf(pz), f2tf(pw));
            *(uint2*)&Ps[r0*68 + nt*8 + 2*c] = u0;
            *(uint2*)&Ps[r1*68 + nt*8 + 2*c] = u1;
        }
        rs0 += __shfl_xor_sync(0xffffffffu, rs0, 1);
        rs0 += __shfl_xor_sync(0xffffffffu, rs0, 2);
        rs1 += __shfl_xor_sync(0xffffffffu, rs1, 1);
        rs1 += __shfl_xor_sync(0xffffffffu, rs1, 2);
        l0 = l0 * al0 + rs0;
        l1 = l1 * al1 + rs1;
        if (c == 0) { red[r0] = al0; red[r1] = al1; }
        __syncthreads();   // Ps + alpha visible to PV layout

        // rescale O (PV layout rows: wm2*32 + mt*16 + {g, g+8})
        float af0 = red[wm2*32      + g], af1 = red[wm2*32      + g + 8];
        float af2 = red[wm2*32 + 16 + g], af3 = red[wm2*32 + 16 + g + 8];
        #pragma unroll
        for (int nt = 0; nt < 8; ++nt) {
            oacc[0][nt].x *= af0; oacc[0][nt].y *= af0;
            oacc[0][nt].z *= af1; oacc[0][nt].w *= af1;
            oacc[1][nt].x *= af2; oacc[1][nt].y *= af2;
            oacc[1][nt].z *= af3; oacc[1][nt].w *= af3;
        }

        // O += P @ V  (warp: 32 rows x 64 cols)
        #pragma unroll
        for (int k8 = 0; k8 < 8; ++k8) {
            int kk = k8 * 8;
            unsigned pa[2][4];
            #pragma unroll
            for (int mt = 0; mt < 2; ++mt) {
                int r = wm2*32 + mt*16 + g;
                pa[mt][0] = Ps[r*68 + kk + c];
                pa[mt][1] = Ps[(r+8)*68 + kk + c];
                pa[mt][2] = Ps[r*68 + kk + c + 4];
                pa[mt][3] = Ps[(r+8)*68 + kk + c + 4];
            }
            #pragma unroll
            for (int nt = 0; nt < 8; ++nt) {
                unsigned b0 = Vs[(kk+c  )*132 + wn2*64 + nt*8 + g];
                unsigned b1 = Vs[(kk+c+4)*132 + wn2*64 + nt*8 + g];
                mma8(oacc[0][nt], pa[0][0], pa[0][1], pa[0][2], pa[0][3], b0, b1);
                mma8(oacc[1][nt], pa[1][0], pa[1][1], pa[1][2], pa[1][3], b0, b1);
            }
        }
    }

    // final normalization: pass l across layouts via smem
    __syncthreads();
    if (c == 0) { red[wbase + g] = l0; red[wbase + g + 8] = l1; }
    __syncthreads();
    float inv0 = 1.f / red[wm2*32      + g], inv1 = 1.f / red[wm2*32      + g + 8];
    float inv2 = 1.f / red[wm2*32 + 16 + g], inv3 = 1.f / red[wm2*32 + 16 + g + 8];

    const int bb = bh >> 3, hh = bh & 7;
    #pragma unroll
    for (int mt = 0; mt < 2; ++mt) {
        float iv0 = (mt == 0) ? inv0 : inv2;
        float iv1 = (mt == 0) ? inv1 : inv3;
        int t0 = qbase + wm2*32 + mt*16 + g;
        #pragma unroll
        for (int nt = 0; nt < 8; ++nt) {
            int d = wn2*64 + nt*8 + 2*c;
            float* p0 = g_ao + ((size_t)(bb*T_ + t0))*(H_*D_) + hh*128 + d;
            *(float2*)p0 = make_float2(oacc[mt][nt].x * iv0, oacc[mt][nt].y * iv0);
            float* p1 = g_ao + ((size_t)(bb*T_ + t0 + 8))*(H_*D_) + hh*128 + d;
            *(float2*)p1 = make_float2(oacc[mt][nt].z * iv1, oacc[mt][nt].w * iv1);
        }
    }
}

// ---------------------------------------------------------------------------
// Kernel 3: output projection, tf32 MMA.  AO[8192,1024] @ Wu[1024,128] + bu
// grid (128), 256 threads.  BM=64, BN=128, BK=64 x16; warp tile 16x64 (4x2).
// ---------------------------------------------------------------------------
__global__ __launch_bounds__(256, 1)
void proj_kernel(const float* __restrict__ Wu, const float* __restrict__ bu,
                 float* __restrict__ out)
{
    extern __shared__ unsigned smu[];
    unsigned* As = smu;           // [64][68]
    unsigned* Bs = smu + 64*68;   // [64][132]

    const int by  = blockIdx.x;
    const int tid = threadIdx.x;
    const int wid = tid >> 5, lane = tid & 31;
    const int g = lane >> 2, c = lane & 3;
    const int wm = wid >> 1, wn = wid & 1;

    float4 acc[8];
    #pragma unroll
    for (int j = 0; j < 8; ++j) acc[j] = make_float4(0.f, 0.f, 0.f, 0.f);

    for (int kc = 0; kc < 16; ++kc) {
        __syncthreads();
        #pragma unroll
        for (int it = 0; it < 4; ++it) {
            int lin = it * 256 + tid;
            int m = lin >> 4, c4 = lin & 15;
            float4 v4 = *(const float4*)(g_ao + (size_t)(by*64 + m)*1024
                                              + kc*64 + c4*4);
            unsigned* d = As + m*68 + c4*4;
            d[0]=f2tf(v4.x); d[1]=f2tf(v4.y); d[2]=f2tf(v4.z); d[3]=f2tf(v4.w);
        }
        #pragma unroll
        for (int it = 0; it < 8; ++it) {
            int lin = it * 256 + tid;
            int k = lin >> 5, n4 = lin & 31;
            float4 v4 = *(const float4*)(Wu + (size_t)(kc*64 + k)*128 + n4*4);
            unsigned* d = Bs + k*132 + n4*4;
            d[0]=f2tf(v4.x); d[1]=f2tf(v4.y); d[2]=f2tf(v4.z); d[3]=f2tf(v4.w);
        }
        __syncthreads();

        #pragma unroll
        for (int k8 = 0; k8 < 8; ++k8) {
            int kk = k8 * 8;
            int r = wm*16 + g;
            unsigned a0 = As[r*68 + kk + c];
            unsigned a1 = As[(r+8)*68 + kk + c];
            unsigned a2 = As[r*68 + kk + c + 4];
            unsigned a3 = As[(r+8)*68 + kk + c + 4];
            #pragma unroll
            for (int nt = 0; nt < 8; ++nt) {
                unsigned b0 = Bs[(kk+c  )*132 + wn*64 + nt*8 + g];
                unsigned b1 = Bs[(kk+c+4)*132 + wn*64 + nt*8 + g];
                mma8(acc[nt], a0, a1, a2, a3, b0, b1);
            }
        }
    }

    #pragma unroll
    for (int nt = 0; nt < 8; ++nt) {
        int d = wn*64 + nt*8 + 2*c;
        float bv0 = bu[d], bv1 = bu[d + 1];
        int m0 = by*64 + wm*16 + g;
        *(float2*)(out + (size_t)m0*128 + d) =
            make_float2(acc[nt].x + bv0, acc[nt].y + bv1);
        *(float2*)(out + (size_t)(m0 + 8)*128 + d) =
            make_float2(acc[nt].z + bv0, acc[nt].w + bv1);
    }
}

// ---------------------------------------------------------------------------
extern "C" void kernel_launch(void* const* d_in, const int* in_sizes, int n_in,
                              void* d_out, int out_size)
{
    const float* x  = (const float*)d_in[0];
    const float* Wq = (const float*)d_in[1];
    const float* Wk = (const float*)d_in[2];
    const float* Wv = (const float*)d_in[3];
    const float* Wu = (const float*)d_in[4];
    const float* bu = (const float*)d_in[5];
    float* out = (float*)d_out;

    const int SMEM1 = (128*68 + 64*132) * (int)sizeof(unsigned);                       // 68608
    const int SMEM2 = (128*132 + 64*132 + 64*132 + 128*68 + 128) * (int)sizeof(unsigned); // 170496
    const int SMEM3 = (64*68 + 64*132) * (int)sizeof(unsigned);                        // 51200

    cudaFuncSetAttribute(qkv_kernel,  cudaFuncAttributeMaxDynamicSharedMemorySize, SMEM1);
    cudaFuncSetAttribute(attn_kernel, cudaFuncAttributeMaxDynamicSharedMemorySize, SMEM2);
    cudaFuncSetAttribute(proj_kernel, cudaFuncAttributeMaxDynamicSharedMemorySize, SMEM3);

    qkv_kernel<<<dim3(8, 64, 3), 256, SMEM1>>>(x, Wq, Wk, Wv);
    attn_kernel<<<dim3(16, 32), 256, SMEM2>>>();
    proj_kernel<<<dim3(128), 256, SMEM3>>>(Wu, bu, out);
}

// round 9
// speedup vs baseline: 3.1841x; 1.1417x over previous
#include <cuda_runtime.h>
#include <math.h>
#include <stdint.h>

#define B_  4
#define T_  2048
#define D_  128
#define H_  8
#define BH_ (B_*H_)
#define NEGINF (-1e30f)

// scratch (device globals -- no allocation allowed)
__device__ float g_q [BH_*T_*D_];
__device__ float g_k [BH_*T_*D_];
__device__ float g_v [BH_*T_*D_];
__device__ float g_ao[B_*T_*H_*D_];

__device__ __forceinline__ unsigned f2tf(float f){
    unsigned u; asm("cvt.rna.tf32.f32 %0, %1;" : "=r"(u) : "f"(f)); return u;
}
__device__ __forceinline__ uint4 f2tf4(float4 v){
    return make_uint4(f2tf(v.x), f2tf(v.y), f2tf(v.z), f2tf(v.w));
}

__device__ __forceinline__ void mma8(float4& d,
    unsigned a0, unsigned a1, unsigned a2, unsigned a3,
    unsigned b0, unsigned b1)
{
    asm volatile(
        "mma.sync.aligned.m16n8k8.row.col.f32.tf32.tf32.f32 "
        "{%0,%1,%2,%3},{%4,%5,%6,%7},{%8,%9},{%0,%1,%2,%3};"
        : "+f"(d.x), "+f"(d.y), "+f"(d.z), "+f"(d.w)
        : "r"(a0), "r"(a1), "r"(a2), "r"(a3), "r"(b0), "r"(b1));
}

// ---------------------------------------------------------------------------
// Kernel 1: fused QKV projection, tf32 MMA.
// X[8192,128] @ W[128,1024] x3.  grid (8 heads, 64 row tiles, 3 mats), 256 thr.
// Full-depth tiles loaded in ONE phase (max MLP), single sync, K=128 compute.
// Xs stride 132 (conflict-free A), Ws stride 136 (conflict-free B).
// ---------------------------------------------------------------------------
__global__ __launch_bounds__(256, 1)
void qkv_kernel(const float* __restrict__ x,  const float* __restrict__ Wq,
                const float* __restrict__ Wk, const float* __restrict__ Wv)
{
    extern __shared__ unsigned smu[];
    unsigned* Xs = smu;             // [128][132]
    unsigned* Ws = smu + 128*132;   // [128][136]

    const int bx = blockIdx.x;     // head (128-col tile)
    const int by = blockIdx.y;     // 128-row tile
    const int mat = blockIdx.z;
    const float* W = (mat == 0) ? Wq : (mat == 1 ? Wk : Wv);
    float* outp    = (mat == 0) ? g_q : (mat == 1 ? g_k : g_v);
    const float vs = (mat == 2) ? 0.29730177875068026f : 1.0f; // 128^-0.25

    const int tid = threadIdx.x;
    const int wid = tid >> 5, lane = tid & 31;
    const int g = lane >> 2, c = lane & 3;
    const int wm = wid >> 1, wn = wid & 1;

    // one-shot loads: X [128x128], W [128x128]
    #pragma unroll
    for (int it = 0; it < 16; ++it) {
        int lin = it * 256 + tid;
        int m = lin >> 5, c4 = lin & 31;
        float4 v4 = *(const float4*)(x + (size_t)(by*128 + m)*128 + c4*4);
        *(uint4*)(Xs + m*132 + c4*4) = f2tf4(v4);
    }
    #pragma unroll
    for (int it = 0; it < 16; ++it) {
        int lin = it * 256 + tid;
        int k = lin >> 5, n4 = lin & 31;
        float4 v4 = *(const float4*)(W + (size_t)k*1024 + bx*128 + n4*4);
        *(uint4*)(Ws + k*136 + n4*4) = f2tf4(v4);
    }
    __syncthreads();

    float4 acc[2][8];
    #pragma unroll
    for (int i = 0; i < 2; ++i)
        #pragma unroll
        for (int j = 0; j < 8; ++j) acc[i][j] = make_float4(0.f, 0.f, 0.f, 0.f);

    #pragma unroll
    for (int k8 = 0; k8 < 16; ++k8) {
        int kk = k8 * 8;
        unsigned a[2][4];
        #pragma unroll
        for (int mt = 0; mt < 2; ++mt) {
            int r = wm*32 + mt*16 + g;
            a[mt][0] = Xs[r*132 + kk + c];
            a[mt][1] = Xs[(r+8)*132 + kk + c];
            a[mt][2] = Xs[r*132 + kk + c + 4];
            a[mt][3] = Xs[(r+8)*132 + kk + c + 4];
        }
        #pragma unroll
        for (int nt = 0; nt < 8; ++nt) {
            unsigned b0 = Ws[(kk+c  )*136 + wn*64 + nt*8 + g];
            unsigned b1 = Ws[(kk+c+4)*136 + wn*64 + nt*8 + g];
            mma8(acc[0][nt], a[0][0], a[0][1], a[0][2], a[0][3], b0, b1);
            mma8(acc[1][nt], a[1][0], a[1][1], a[1][2], a[1][3], b0, b1);
        }
    }

    // epilogue: out layout [b*H+h][t][d],  h == bx exactly (128-col tile)
    #pragma unroll
    for (int mt = 0; mt < 2; ++mt) {
        int mg0 = by*128 + wm*32 + mt*16 + g;
        int b0i = mg0 >> 11, t0 = mg0 & (T_ - 1);
        int mg1 = mg0 + 8;
        int b1i = mg1 >> 11, t1 = mg1 & (T_ - 1);
        #pragma unroll
        for (int nt = 0; nt < 8; ++nt) {
            int d = wn*64 + nt*8 + 2*c;
            float* p0 = outp + ((size_t)(b0i*H_ + bx)*T_ + t0)*D_ + d;
            *(float2*)p0 = make_float2(acc[mt][nt].x * vs, acc[mt][nt].y * vs);
            float* p1 = outp + ((size_t)(b1i*H_ + bx)*T_ + t1)*D_ + d;
            *(float2*)p1 = make_float2(acc[mt][nt].z * vs, acc[mt][nt].w * vs);
        }
    }
}

// ---------------------------------------------------------------------------
// Kernel 2: causal flash attention, tf32 MMA, software-pipelined K/V loads.
// grid (16 q-tiles, 32 bh), 256 threads.  BM=128 queries, BN=64 keys/step.
// K_{n+1} LDG before S-GEMM (latency under S), STS after post-S barrier.
// V_{n+1} LDG after post-S barrier (latency under softmax+PV), STS after
// post-PV barrier.  Vs stride 136 -> conflict-free PV B-operand.
// ---------------------------------------------------------------------------
__global__ __launch_bounds__(256, 1)
void attn_kernel()
{
    extern __shared__ unsigned smu[];
    unsigned* Qs = smu;                    // [128][132] tf32
    unsigned* Ks = Qs + 128*132;           // [ 64][132] tf32
    unsigned* Vs = Ks +  64*132;           // [ 64][136] tf32
    unsigned* Ps = Vs +  64*136;           // [128][ 68] tf32
    float*   red = (float*)(Ps + 128*68);  // [128] alpha, then l

    const int bh    = blockIdx.y;
    const int qi    = (int)gridDim.x - 1 - (int)blockIdx.x;  // big tiles first
    const int qbase = qi * 128;
    const int tid   = threadIdx.x;
    const int wid   = tid >> 5, lane = tid & 31;
    const int g = lane >> 2, c = lane & 3;
    const int wbase = wid * 16;              // S-layout row base
    const int wm2 = wid >> 1, wn2 = wid & 1; // PV layout
    const int lm = tid >> 5, lc4 = tid & 31; // load indexing (per-iter rows)

    const float* qg = g_q + ((size_t)bh * T_ + qbase) * D_;
    const float* kg = g_k + (size_t)bh * T_ * D_;
    const float* vg = g_v + (size_t)bh * T_ * D_;

    // load Q tile once (tf32)
    #pragma unroll
    for (int it = 0; it < 16; ++it) {
        int lin = it * 256 + tid;
        int m = lin >> 5, c4 = lin & 31;
        float4 v4 = *(const float4*)(qg + m*128 + c4*4);
        *(uint4*)(Qs + m*132 + c4*4) = f2tf4(v4);
    }

    float4 kreg[8], vreg[8];
    // prologue: K0, V0
    #pragma unroll
    for (int it = 0; it < 8; ++it) {
        int m = it*8 + lm;
        kreg[it] = *(const float4*)(kg + m*128 + lc4*4);
        vreg[it] = *(const float4*)(vg + m*128 + lc4*4);
    }
    #pragma unroll
    for (int it = 0; it < 8; ++it) {
        int m = it*8 + lm;
        *(uint4*)(Ks + m*132 + lc4*4) = f2tf4(kreg[it]);
        *(uint4*)(Vs + m*136 + lc4*4) = f2tf4(vreg[it]);
    }
    __syncthreads();

    float m0 = NEGINF, m1 = NEGINF, l0 = 0.f, l1 = 0.f;
    float4 oacc[2][8];
    #pragma unroll
    for (int i = 0; i < 2; ++i)
        #pragma unroll
        for (int j = 0; j < 8; ++j) oacc[i][j] = make_float4(0.f, 0.f, 0.f, 0.f);

    const int   ntiles = 2 * qi + 2;
    const float sscale = 0.088388347648318447f;   // 128^-0.5

    for (int n = 0; n < ntiles; ++n) {
        const bool pre = (n + 1 < ntiles);
        // prefetch K_{n+1}: latency hidden under the S GEMM
        if (pre) {
            const float* kt = kg + (size_t)(n+1) * 64 * D_;
            #pragma unroll
            for (int it = 0; it < 8; ++it)
                kreg[it] = *(const float4*)(kt + (it*8 + lm)*128 + lc4*4);
        }

        // S = Q K^T : warp rows [wbase, wbase+16), all 64 cols
        float4 sacc[8];
        #pragma unroll
        for (int nt = 0; nt < 8; ++nt) sacc[nt] = make_float4(0.f, 0.f, 0.f, 0.f);

        #pragma unroll
        for (int k8 = 0; k8 < 16; ++k8) {
            int kk = k8 * 8;
            unsigned a0 = Qs[(wbase+g  )*132 + kk + c];
            unsigned a1 = Qs[(wbase+g+8)*132 + kk + c];
            unsigned a2 = Qs[(wbase+g  )*132 + kk + c + 4];
            unsigned a3 = Qs[(wbase+g+8)*132 + kk + c + 4];
            #pragma unroll
            for (int nt = 0; nt < 8; ++nt) {
                unsigned b0 = Ks[(nt*8+g)*132 + kk + c];
                unsigned b1 = Ks[(nt*8+g)*132 + kk + c + 4];
                mma8(sacc[nt], a0, a1, a2, a3, b0, b1);
            }
        }
        __syncthreads();   // bar1: all warps done reading Ks

        // stage K_{n+1} into Ks; prefetch V_{n+1} (latency under softmax+PV)
        if (pre) {
            #pragma unroll
            for (int it = 0; it < 8; ++it)
                *(uint4*)(Ks + (it*8 + lm)*132 + lc4*4) = f2tf4(kreg[it]);
            const float* vt = vg + (size_t)(n+1) * 64 * D_;
            #pragma unroll
            for (int it = 0; it < 8; ++it)
                vreg[it] = *(const float4*)(vt + (it*8 + lm)*128 + lc4*4);
        }

        // scale
        #pragma unroll
        for (int nt = 0; nt < 8; ++nt) {
            sacc[nt].x *= sscale; sacc[nt].y *= sscale;
            sacc[nt].z *= sscale; sacc[nt].w *= sscale;
        }
        // causal mask (only last two tiles can touch the diagonal)
        if (n >= 2 * qi) {
            int rg0 = qbase + wbase + g, rg1 = rg0 + 8;
            #pragma unroll
            for (int nt = 0; nt < 8; ++nt) {
                int c0 = n*64 + nt*8 + 2*c;
                if (c0     > rg0) sacc[nt].x = NEGINF;
                if (c0 + 1 > rg0) sacc[nt].y = NEGINF;
                if (c0     > rg1) sacc[nt].z = NEGINF;
                if (c0 + 1 > rg1) sacc[nt].w = NEGINF;
            }
        }

        // online softmax: rows r0 = wbase+g, r1 = r0+8 (reduce over 4-lane group)
        float mx0 = NEGINF, mx1 = NEGINF;
        #pragma unroll
        for (int nt = 0; nt < 8; ++nt) {
            mx0 = fmaxf(mx0, fmaxf(sacc[nt].x, sacc[nt].y));
            mx1 = fmaxf(mx1, fmaxf(sacc[nt].z, sacc[nt].w));
        }
        mx0 = fmaxf(mx0, __shfl_xor_sync(0xffffffffu, mx0, 1));
        mx0 = fmaxf(mx0, __shfl_xor_sync(0xffffffffu, mx0, 2));
        mx1 = fmaxf(mx1, __shfl_xor_sync(0xffffffffu, mx1, 1));
        mx1 = fmaxf(mx1, __shfl_xor_sync(0xffffffffu, mx1, 2));

        float mn0 = fmaxf(m0, mx0), mn1 = fmaxf(m1, mx1);
        float al0 = __expf(m0 - mn0), al1 = __expf(m1 - mn1);
        m0 = mn0; m1 = mn1;

        int r0 = wbase + g, r1 = r0 + 8;
        float rs0 = 0.f, rs1 = 0.f;
        #pragma unroll
        for (int nt = 0; nt < 8; ++nt) {
            float px = __expf(sacc[nt].x - mn0);
            float py = __expf(sacc[nt].y - mn0);
            float pz = __expf(sacc[nt].z - mn1);
            float pw = __expf(sacc[nt].w - mn1);
            rs0 += px + py; rs1 += pz + pw;
            uint2 u0 = make_uint2(f2tf(px), f2tf(py));
            uint2 u1 = make_uint2(f2tf(pz), f2tf(pw));
            *(uint2*)&Ps[r0*68 + nt*8 + 2*c] = u0;
            *(uint2*)&Ps[r1*68 + nt*8 + 2*c] = u1;
        }
        rs0 += __shfl_xor_sync(0xffffffffu, rs0, 1);
        rs0 += __shfl_xor_sync(0xffffffffu, rs0, 2);
        rs1 += __shfl_xor_sync(0xffffffffu, rs1, 1);
        rs1 += __shfl_xor_sync(0xffffffffu, rs1, 2);
        l0 = l0 * al0 + rs0;
        l1 = l1 * al1 + rs1;
        if (c == 0) { red[r0] = al0; red[r1] = al1; }
        __syncthreads();   // bar2: Ps + alpha visible (Ks staging ordered too)

        // rescale O (PV layout rows: wm2*32 + mt*16 + {g, g+8})
        float af0 = red[wm2*32      + g], af1 = red[wm2*32      + g + 8];
        float af2 = red[wm2*32 + 16 + g], af3 = red[wm2*32 + 16 + g + 8];
        #pragma unroll
        for (int nt = 0; nt < 8; ++nt) {
            oacc[0][nt].x *= af0; oacc[0][nt].y *= af0;
            oacc[0][nt].z *= af1; oacc[0][nt].w *= af1;
            oacc[1][nt].x *= af2; oacc[1][nt].y *= af2;
            oacc[1][nt].z *= af3; oacc[1][nt].w *= af3;
        }

        // O += P @ V  (warp: 32 rows x 64 cols)
        #pragma unroll
        for (int k8 = 0; k8 < 8; ++k8) {
            int kk = k8 * 8;
            unsigned pa[2][4];
            #pragma unroll
            for (int mt = 0; mt < 2; ++mt) {
                int r = wm2*32 + mt*16 + g;
                pa[mt][0] = Ps[r*68 + kk + c];
                pa[mt][1] = Ps[(r+8)*68 + kk + c];
                pa[mt][2] = Ps[r*68 + kk + c + 4];
                pa[mt][3] = Ps[(r+8)*68 + kk + c + 4];
            }
            #pragma unroll
            for (int nt = 0; nt < 8; ++nt) {
                unsigned b0 = Vs[(kk+c  )*136 + wn2*64 + nt*8 + g];
                unsigned b1 = Vs[(kk+c+4)*136 + wn2*64 + nt*8 + g];
                mma8(oacc[0][nt], pa[0][0], pa[0][1], pa[0][2], pa[0][3], b0, b1);
                mma8(oacc[1][nt], pa[1][0], pa[1][1], pa[1][2], pa[1][3], b0, b1);
            }
        }
        __syncthreads();   // bar3: all warps done reading Vs

        // stage V_{n+1} into Vs
        if (pre) {
            #pragma unroll
            for (int it = 0; it < 8; ++it)
                *(uint4*)(Vs + (it*8 + lm)*136 + lc4*4) = f2tf4(vreg[it]);
        }
    }

    // final normalization: pass l across layouts via smem
    __syncthreads();
    if (c == 0) { red[wbase + g] = l0; red[wbase + g + 8] = l1; }
    __syncthreads();
    float inv0 = 1.f / red[wm2*32      + g], inv1 = 1.f / red[wm2*32      + g + 8];
    float inv2 = 1.f / red[wm2*32 + 16 + g], inv3 = 1.f / red[wm2*32 + 16 + g + 8];

    const int bb = bh >> 3, hh = bh & 7;
    #pragma unroll
    for (int mt = 0; mt < 2; ++mt) {
        float iv0 = (mt == 0) ? inv0 : inv2;
        float iv1 = (mt == 0) ? inv1 : inv3;
        int t0 = qbase + wm2*32 + mt*16 + g;
        #pragma unroll
        for (int nt = 0; nt < 8; ++nt) {
            int d = wn2*64 + nt*8 + 2*c;
            float* p0 = g_ao + ((size_t)(bb*T_ + t0))*(H_*D_) + hh*128 + d;
            *(float2*)p0 = make_float2(oacc[mt][nt].x * iv0, oacc[mt][nt].y * iv0);
            float* p1 = g_ao + ((size_t)(bb*T_ + t0 + 8))*(H_*D_) + hh*128 + d;
            *(float2*)p1 = make_float2(oacc[mt][nt].z * iv1, oacc[mt][nt].w * iv1);
        }
    }
}

// ---------------------------------------------------------------------------
// Kernel 3: output projection, tf32 MMA, register double-buffered k-chunks.
// AO[8192,1024] @ Wu[1024,128] + bu.  grid (128), 256 threads.
// BM=64, BN=128, BK=64 x16; warp tile 16x64 (4x2).  Bs stride 136.
// ---------------------------------------------------------------------------
__global__ __launch_bounds__(256, 1)
void proj_kernel(const float* __restrict__ Wu, const float* __restrict__ bu,
                 float* __restrict__ out)
{
    extern __shared__ unsigned smu[];
    unsigned* As = smu;           // [64][68]
    unsigned* Bs = smu + 64*68;   // [64][136]

    const int by  = blockIdx.x;
    const int tid = threadIdx.x;
    const int wid = tid >> 5, lane = tid & 31;
    const int g = lane >> 2, c = lane & 3;
    const int wm = wid >> 1, wn = wid & 1;

    float4 acc[8];
    #pragma unroll
    for (int j = 0; j < 8; ++j) acc[j] = make_float4(0.f, 0.f, 0.f, 0.f);

    float4 areg[4], breg[8];
    // prologue: chunk 0
    #pragma unroll
    for (int it = 0; it < 4; ++it) {
        int lin = it * 256 + tid;
        int m = lin >> 4, c4 = lin & 15;
        areg[it] = *(const float4*)(g_ao + (size_t)(by*64 + m)*1024 + c4*4);
    }
    #pragma unroll
    for (int it = 0; it < 8; ++it) {
        int lin = it * 256 + tid;
        int k = lin >> 5, n4 = lin & 31;
        breg[it] = *(const float4*)(Wu + (size_t)k*128 + n4*4);
    }

    for (int kc = 0; kc < 16; ++kc) {
        __syncthreads();   // previous compute done reading smem
        #pragma unroll
        for (int it = 0; it < 4; ++it) {
            int lin = it * 256 + tid;
            int m = lin >> 4, c4 = lin & 15;
            *(uint4*)(As + m*68 + c4*4) = f2tf4(areg[it]);
        }
        #pragma unroll
        for (int it = 0; it < 8; ++it) {
            int lin = it * 256 + tid;
            int k = lin >> 5, n4 = lin & 31;
            *(uint4*)(Bs + k*136 + n4*4) = f2tf4(breg[it]);
        }
        __syncthreads();

        // prefetch next chunk (latency hidden under compute)
        if (kc < 15) {
            #pragma unroll
            for (int it = 0; it < 4; ++it) {
                int lin = it * 256 + tid;
                int m = lin >> 4, c4 = lin & 15;
                areg[it] = *(const float4*)(g_ao + (size_t)(by*64 + m)*1024
                                                 + (kc+1)*64 + c4*4);
            }
            #pragma unroll
            for (int it = 0; it < 8; ++it) {
                int lin = it * 256 + tid;
                int k = lin >> 5, n4 = lin & 31;
                breg[it] = *(const float4*)(Wu + (size_t)((kc+1)*64 + k)*128 + n4*4);
            }
        }

        #pragma unroll
        for (int k8 = 0; k8 < 8; ++k8) {
            int kk = k8 * 8;
            int r = wm*16 + g;
            unsigned a0 = As[r*68 + kk + c];
            unsigned a1 = As[(r+8)*68 + kk + c];
            unsigned a2 = As[r*68 + kk + c + 4];
            unsigned a3 = As[(r+8)*68 + kk + c + 4];
            #pragma unroll
            for (int nt = 0; nt < 8; ++nt) {
                unsigned b0 = Bs[(kk+c  )*136 + wn*64 + nt*8 + g];
                unsigned b1 = Bs[(kk+c+4)*136 + wn*64 + nt*8 + g];
                mma8(acc[nt], a0, a1, a2, a3, b0, b1);
            }
        }
    }

    #pragma unroll
    for (int nt = 0; nt < 8; ++nt) {
        int d = wn*64 + nt*8 + 2*c;
        float bv0 = bu[d], bv1 = bu[d + 1];
        int m0 = by*64 + wm*16 + g;
        *(float2*)(out + (size_t)m0*128 + d) =
            make_float2(acc[nt].x + bv0, acc[nt].y + bv1);
        *(float2*)(out + (size_t)(m0 + 8)*128 + d) =
            make_float2(acc[nt].z + bv0, acc[nt].w + bv1);
    }
}

// ---------------------------------------------------------------------------
extern "C" void kernel_launch(void* const* d_in, const int* in_sizes, int n_in,
                              void* d_out, int out_size)
{
    const float* x  = (const float*)d_in[0];
    const float* Wq = (const float*)d_in[1];
    const float* Wk = (const float*)d_in[2];
    const float* Wv = (const float*)d_in[3];
    const float* Wu = (const float*)d_in[4];
    const float* bu = (const float*)d_in[5];
    float* out = (float*)d_out;

    const int SMEM1 = (128*132 + 128*136) * (int)sizeof(unsigned);                 // 137216
    const int SMEM2 = (128*132 + 64*132 + 64*136 + 128*68 + 128) * (int)sizeof(unsigned); // 171520
    const int SMEM3 = (64*68 + 64*136) * (int)sizeof(unsigned);                    // 52224

    cudaFuncSetAttribute(qkv_kernel,  cudaFuncAttributeMaxDynamicSharedMemorySize, SMEM1);
    cudaFuncSetAttribute(attn_kernel, cudaFuncAttributeMaxDynamicSharedMemorySize, SMEM2);
    cudaFuncSetAttribute(proj_kernel, cudaFuncAttributeMaxDynamicSharedMemorySize, SMEM3);

    qkv_kernel<<<dim3(8, 64, 3), 256, SMEM1>>>(x, Wq, Wk, Wv);
    attn_kernel<<<dim3(16, 32), 256, SMEM2>>>();
    proj_kernel<<<dim3(128), 256, SMEM3>>>(Wu, bu, out);
}

// round 11
// speedup vs baseline: 3.3958x; 1.0665x over previous
#include <cuda_runtime.h>
#include <math.h>
#include <stdint.h>

#define B_  4
#define T_  2048
#define D_  128
#define H_  8
#define BH_ (B_*H_)
#define NEGINF (-1e30f)

// scratch (device globals -- no allocation allowed)
__device__ float g_q [BH_*T_*D_];
__device__ float g_k [BH_*T_*D_];
__device__ float g_v [BH_*T_*D_];
__device__ float g_ao[B_*T_*H_*D_];
// pre-rounded tf32 operands
__device__ float g_x [B_*T_*D_];
__device__ float g_wq[D_*H_*D_];
__device__ float g_wk[D_*H_*D_];
__device__ float g_wv[D_*H_*D_];
__device__ float g_wu[H_*D_*D_];

__device__ __forceinline__ unsigned f2tf(float f){
    unsigned u; asm("cvt.rna.tf32.f32 %0, %1;" : "=r"(u) : "f"(f)); return u;
}
__device__ __forceinline__ uint4 f2tf4(float4 v){
    return make_uint4(f2tf(v.x), f2tf(v.y), f2tf(v.z), f2tf(v.w));
}
__device__ __forceinline__ uint4 f4bits(float4 v){
    return make_uint4(__float_as_uint(v.x), __float_as_uint(v.y),
                      __float_as_uint(v.z), __float_as_uint(v.w));
}
__device__ __forceinline__ uint32_t saddr(const void* p){
    return (uint32_t)__cvta_generic_to_shared(p);
}
__device__ __forceinline__ void cpa16(uint32_t dst, const void* src){
    asm volatile("cp.async.cg.shared.global [%0], [%1], 16;" :: "r"(dst), "l"(src));
}
#define CP_COMMIT  asm volatile("cp.async.commit_group;")
#define CP_WAIT0   asm volatile("cp.async.wait_group 0;")
#define CP_WAIT1   asm volatile("cp.async.wait_group 1;")

__device__ __forceinline__ void mma8(float4& d,
    unsigned a0, unsigned a1, unsigned a2, unsigned a3,
    unsigned b0, unsigned b1)
{
    asm volatile(
        "mma.sync.aligned.m16n8k8.row.col.f32.tf32.tf32.f32 "
        "{%0,%1,%2,%3},{%4,%5,%6,%7},{%8,%9},{%0,%1,%2,%3};"
        : "+f"(d.x), "+f"(d.y), "+f"(d.z), "+f"(d.w)
        : "r"(a0), "r"(a1), "r"(a2), "r"(a3), "r"(b0), "r"(b1));
}

// ---------------------------------------------------------------------------
// Kernel 0: pre-round inputs to tf32 (Wv gets 128^-0.25 baked in).
// grid (128, 5), 256 threads.
// ---------------------------------------------------------------------------
__global__ __launch_bounds__(256, 4)
void prep_kernel(const float* __restrict__ x,  const float* __restrict__ wq,
                 const float* __restrict__ wk, const float* __restrict__ wv,
                 const float* __restrict__ wu)
{
    const int seg = blockIdx.y;
    const float* src; float* dst; int n4; float s = 1.0f;
    if      (seg == 0) { src = x;  dst = g_x;  n4 = (B_*T_*D_)/4; }
    else if (seg == 1) { src = wq; dst = g_wq; n4 = (D_*H_*D_)/4; }
    else if (seg == 2) { src = wk; dst = g_wk; n4 = (D_*H_*D_)/4; }
    else if (seg == 3) { src = wv; dst = g_wv; n4 = (D_*H_*D_)/4; s = 0.29730177875068026f; }
    else               { src = wu; dst = g_wu; n4 = (H_*D_*D_)/4; }

    for (int i = blockIdx.x * blockDim.x + threadIdx.x; i < n4;
         i += gridDim.x * blockDim.x) {
        float4 v = ((const float4*)src)[i];
        v.x *= s; v.y *= s; v.z *= s; v.w *= s;
        ((uint4*)dst)[i] = f2tf4(v);
    }
}

// ---------------------------------------------------------------------------
// Kernel 1: fused QKV projection, tf32 MMA, cp.async, 2 CTAs/SM.
// g_x[8192,128] @ g_w*[128,1024].  grid (16 64-col tiles, 64 row tiles, 3),
// 256 thr.  Block tile 128x64, warp tile 32x32 (4x2 warps).
// Xs stride 132, Ws stride 72 (both conflict-free).
// ---------------------------------------------------------------------------
__global__ __launch_bounds__(256, 2)
void qkv_kernel()
{
    extern __shared__ unsigned smu[];
    unsigned* Xs = smu;             // [128][132]
    unsigned* Ws = smu + 128*132;   // [128][72]

    const int bx = blockIdx.x;     // 64-col tile (0..15)
    const int by = blockIdx.y;     // 128-row tile
    const int mat = blockIdx.z;
    const float* Wg = (mat == 0) ? g_wq : (mat == 1 ? g_wk : g_wv);
    float* outp     = (mat == 0) ? g_q  : (mat == 1 ? g_k  : g_v);

    const int tid = threadIdx.x;
    const int wid = tid >> 5, lane = tid & 31;
    const int g = lane >> 2, c = lane & 3;
    const int wm = wid >> 2, wn = wid & 3;   // 2x4 warps: 64-row x 16-col? no:
    // use 4x2: wm = wid>>1 (0..3) rows, wn = wid&1 (0..1) cols of 32
    const int wm2 = wid >> 1, wn2 = wid & 1;

    // async loads: X [128x128], W [128x64]
    #pragma unroll
    for (int it = 0; it < 16; ++it) {
        int lin = it * 256 + tid;
        int m = lin >> 5, c4 = lin & 31;
        cpa16(saddr(Xs + m*132 + c4*4), g_x + (size_t)(by*128 + m)*128 + c4*4);
    }
    #pragma unroll
    for (int it = 0; it < 8; ++it) {
        int lin = it * 256 + tid;
        int k = lin >> 4, n4 = lin & 15;
        cpa16(saddr(Ws + k*72 + n4*4), Wg + (size_t)k*1024 + bx*64 + n4*4);
    }
    CP_COMMIT;
    CP_WAIT0;
    __syncthreads();

    float4 acc[2][4];
    #pragma unroll
    for (int i = 0; i < 2; ++i)
        #pragma unroll
        for (int j = 0; j < 4; ++j) acc[i][j] = make_float4(0.f, 0.f, 0.f, 0.f);

    #pragma unroll
    for (int k8 = 0; k8 < 16; ++k8) {
        int kk = k8 * 8;
        unsigned a[2][4];
        #pragma unroll
        for (int mt = 0; mt < 2; ++mt) {
            int r = wm2*32 + mt*16 + g;
            a[mt][0] = Xs[r*132 + kk + c];
            a[mt][1] = Xs[(r+8)*132 + kk + c];
            a[mt][2] = Xs[r*132 + kk + c + 4];
            a[mt][3] = Xs[(r+8)*132 + kk + c + 4];
        }
        #pragma unroll
        for (int nt = 0; nt < 4; ++nt) {
            unsigned b0 = Ws[(kk+c  )*72 + wn2*32 + nt*8 + g];
            unsigned b1 = Ws[(kk+c+4)*72 + wn2*32 + nt*8 + g];
            mma8(acc[0][nt], a[0][0], a[0][1], a[0][2], a[0][3], b0, b1);
            mma8(acc[1][nt], a[1][0], a[1][1], a[1][2], a[1][3], b0, b1);
        }
    }

    // epilogue: col n = bx*64 + wn2*32 + nt*8 + 2c; h = bx>>1; d = n & 127.
    // outputs tf32-rounded so attn can raw-copy them.
    const int hh = bx >> 1;
    #pragma unroll
    for (int mt = 0; mt < 2; ++mt) {
        int mg0 = by*128 + wm2*32 + mt*16 + g;
        int b0i = mg0 >> 11, t0 = mg0 & (T_ - 1);
        int mg1 = mg0 + 8;
        int b1i = mg1 >> 11, t1 = mg1 & (T_ - 1);
        #pragma unroll
        for (int nt = 0; nt < 4; ++nt) {
            int d = ((bx & 1)*64 + wn2*32 + nt*8 + 2*c);
            float* p0 = outp + ((size_t)(b0i*H_ + hh)*T_ + t0)*D_ + d;
            *(float2*)p0 = make_float2(__uint_as_float(f2tf(acc[mt][nt].x)),
                                       __uint_as_float(f2tf(acc[mt][nt].y)));
            float* p1 = outp + ((size_t)(b1i*H_ + hh)*T_ + t1)*D_ + d;
            *(float2*)p1 = make_float2(__uint_as_float(f2tf(acc[mt][nt].z)),
                                       __uint_as_float(f2tf(acc[mt][nt].w)));
        }
    }
}

// ---------------------------------------------------------------------------
// Kernel 2: causal flash attention, tf32 MMA, cp.async pipelined K/V.
// grid (16 q-tiles, 32 bh), 256 threads.  BM=128, BN=64.
// K_{n+1} cp.async issued after bar1 (arrives during softmax+PV, waited
// before bar3).  V_{n+1} issued after bar3 (waited before bar2 next iter).
// All inputs pre-rounded tf32 -> raw byte copies, no cvt in hot loop.
// ---------------------------------------------------------------------------
__global__ __launch_bounds__(256, 1)
void attn_kernel()
{
    extern __shared__ unsigned smu[];
    unsigned* Qs = smu;                    // [128][132] tf32
    unsigned* Ks = Qs + 128*132;           // [ 64][132] tf32
    unsigned* Vs = Ks +  64*132;           // [ 64][136] tf32
    unsigned* Ps = Vs +  64*136;           // [128][ 68] tf32
    float*   red = (float*)(Ps + 128*68);  // [128] alpha, then l

    const int bh    = blockIdx.y;
    const int qi    = (int)gridDim.x - 1 - (int)blockIdx.x;  // big tiles first
    const int qbase = qi * 128;
    const int tid   = threadIdx.x;
    const int wid   = tid >> 5, lane = tid & 31;
    const int g = lane >> 2, c = lane & 3;
    const int wbase = wid * 16;              // S-layout row base
    const int wm2 = wid >> 1, wn2 = wid & 1; // PV layout
    const int lm = tid >> 5, lc4 = tid & 31; // load indexing

    const float* qg = g_q + ((size_t)bh * T_ + qbase) * D_;
    const float* kg = g_k + (size_t)bh * T_ * D_;
    const float* vg = g_v + (size_t)bh * T_ * D_;

    // prologue: Q, K0, V0 via cp.async (3 groups), single wait+bar
    #pragma unroll
    for (int it = 0; it < 16; ++it) {
        int lin = it * 256 + tid;
        int m = lin >> 5, c4 = lin & 31;
        cpa16(saddr(Qs + m*132 + c4*4), qg + m*128 + c4*4);
    }
    CP_COMMIT;
    #pragma unroll
    for (int it = 0; it < 8; ++it)
        cpa16(saddr(Ks + (it*8 + lm)*132 + lc4*4), kg + (it*8 + lm)*128 + lc4*4);
    CP_COMMIT;
    #pragma unroll
    for (int it = 0; it < 8; ++it)
        cpa16(saddr(Vs + (it*8 + lm)*136 + lc4*4), vg + (it*8 + lm)*128 + lc4*4);
    CP_COMMIT;
    CP_WAIT0;
    __syncthreads();

    float m0 = NEGINF, m1 = NEGINF, l0 = 0.f, l1 = 0.f;
    float4 oacc[2][8];
    #pragma unroll
    for (int i = 0; i < 2; ++i)
        #pragma unroll
        for (int j = 0; j < 8; ++j) oacc[i][j] = make_float4(0.f, 0.f, 0.f, 0.f);

    const int   ntiles = 2 * qi + 2;
    const float sscale = 0.088388347648318447f;   // 128^-0.5

    for (int n = 0; n < ntiles; ++n) {
        const bool pre = (n + 1 < ntiles);

        // S = Q K^T : warp rows [wbase, wbase+16), all 64 cols
        float4 sacc[8];
        #pragma unroll
        for (int nt = 0; nt < 8; ++nt) sacc[nt] = make_float4(0.f, 0.f, 0.f, 0.f);

        #pragma unroll
        for (int k8 = 0; k8 < 16; ++k8) {
            int kk = k8 * 8;
            unsigned a0 = Qs[(wbase+g  )*132 + kk + c];
            unsigned a1 = Qs[(wbase+g+8)*132 + kk + c];
            unsigned a2 = Qs[(wbase+g  )*132 + kk + c + 4];
            unsigned a3 = Qs[(wbase+g+8)*132 + kk + c + 4];
            #pragma unroll
            for (int nt = 0; nt < 8; ++nt) {
                unsigned b0 = Ks[(nt*8+g)*132 + kk + c];
                unsigned b1 = Ks[(nt*8+g)*132 + kk + c + 4];
                mma8(sacc[nt], a0, a1, a2, a3, b0, b1);
            }
        }
        __syncthreads();   // bar1: all warps done reading Ks

        // async-stage K_{n+1} into Ks (arrives during softmax+PV)
        if (pre) {
            const float* kt = kg + (size_t)(n+1) * 64 * D_;
            #pragma unroll
            for (int it = 0; it < 8; ++it)
                cpa16(saddr(Ks + (it*8 + lm)*132 + lc4*4),
                      kt + (it*8 + lm)*128 + lc4*4);
            CP_COMMIT;
        }

        // scale
        #pragma unroll
        for (int nt = 0; nt < 8; ++nt) {
            sacc[nt].x *= sscale; sacc[nt].y *= sscale;
            sacc[nt].z *= sscale; sacc[nt].w *= sscale;
        }
        // causal mask (only last two tiles can touch the diagonal)
        if (n >= 2 * qi) {
            int rg0 = qbase + wbase + g, rg1 = rg0 + 8;
            #pragma unroll
            for (int nt = 0; nt < 8; ++nt) {
                int c0 = n*64 + nt*8 + 2*c;
                if (c0     > rg0) sacc[nt].x = NEGINF;
                if (c0 + 1 > rg0) sacc[nt].y = NEGINF;
                if (c0     > rg1) sacc[nt].z = NEGINF;
                if (c0 + 1 > rg1) sacc[nt].w = NEGINF;
            }
        }

        // online softmax: rows r0 = wbase+g, r1 = r0+8 (4-lane group reduce)
        float mx0 = NEGINF, mx1 = NEGINF;
        #pragma unroll
        for (int nt = 0; nt < 8; ++nt) {
            mx0 = fmaxf(mx0, fmaxf(sacc[nt].x, sacc[nt].y));
            mx1 = fmaxf(mx1, fmaxf(sacc[nt].z, sacc[nt].w));
        }
        mx0 = fmaxf(mx0, __shfl_xor_sync(0xffffffffu, mx0, 1));
        mx0 = fmaxf(mx0, __shfl_xor_sync(0xffffffffu, mx0, 2));
        mx1 = fmaxf(mx1, __shfl_xor_sync(0xffffffffu, mx1, 1));
        mx1 = fmaxf(mx1, __shfl_xor_sync(0xffffffffu, mx1, 2));

        float mn0 = fmaxf(m0, mx0), mn1 = fmaxf(m1, mx1);
        float al0 = __expf(m0 - mn0), al1 = __expf(m1 - mn1);
        m0 = mn0; m1 = mn1;

        int r0 = wbase + g, r1 = r0 + 8;
        float rs0 = 0.f, rs1 = 0.f;
        #pragma unroll
        for (int nt = 0; nt < 8; ++nt) {
            float px = __expf(sacc[nt].x - mn0);
            float py = __expf(sacc[nt].y - mn0);
            float pz = __expf(sacc[nt].z - mn1);
            float pw = __expf(sacc[nt].w - mn1);
            rs0 += px + py; rs1 += pz + pw;
            uint2 u0 = make_uint2(f2tf(px), f2tf(py));
            uint2 u1 = make_uint2(f2tf(pz), f2tf(pw));
            *(uint2*)&Ps[r0*68 + nt*8 + 2*c] = u0;
            *(uint2*)&Ps[r1*68 + nt*8 + 2*c] = u1;
        }
        rs0 += __shfl_xor_sync(0xffffffffu, rs0, 1);
        rs0 += __shfl_xor_sync(0xffffffffu, rs0, 2);
        rs1 += __shfl_xor_sync(0xffffffffu, rs1, 1);
        rs1 += __shfl_xor_sync(0xffffffffu, rs1, 2);
        l0 = l0 * al0 + rs0;
        l1 = l1 * al1 + rs1;
        if (c == 0) { red[r0] = al0; red[r1] = al1; }

        // ensure V_n arrived (oldest pending group); K_{n+1} may still fly
        if (pre) { CP_WAIT1; } else { CP_WAIT0; }
        __syncthreads();   // bar2: Ps + alpha + V_n visible

        // rescale O (PV layout rows: wm2*32 + mt*16 + {g, g+8})
        float af0 = red[wm2*32      + g], af1 = red[wm2*32      + g + 8];
        float af2 = red[wm2*32 + 16 + g], af3 = red[wm2*32 + 16 + g + 8];
        #pragma unroll
        for (int nt = 0; nt < 8; ++nt) {
            oacc[0][nt].x *= af0; oacc[0][nt].y *= af0;
            oacc[0][nt].z *= af1; oacc[0][nt].w *= af1;
            oacc[1][nt].x *= af2; oacc[1][nt].y *= af2;
            oacc[1][nt].z *= af3; oacc[1][nt].w *= af3;
        }

        // O += P @ V  (warp: 32 rows x 64 cols)
        #pragma unroll
        for (int k8 = 0; k8 < 8; ++k8) {
            int kk = k8 * 8;
            unsigned pa[2][4];
            #pragma unroll
            for (int mt = 0; mt < 2; ++mt) {
                int r = wm2*32 + mt*16 + g;
                pa[mt][0] = Ps[r*68 + kk + c];
                pa[mt][1] = Ps[(r+8)*68 + kk + c];
                pa[mt][2] = Ps[r*68 + kk + c + 4];
                pa[mt][3] = Ps[(r+8)*68 + kk + c + 4];
            }
            #pragma unroll
            for (int nt = 0; nt < 8; ++nt) {
                unsigned b0 = Vs[(kk+c  )*136 + wn2*64 + nt*8 + g];
                unsigned b1 = Vs[(kk+c+4)*136 + wn2*64 + nt*8 + g];
                mma8(oacc[0][nt], pa[0][0], pa[0][1], pa[0][2], pa[0][3], b0, b1);
                mma8(oacc[1][nt], pa[1][0], pa[1][1], pa[1][2], pa[1][3], b0, b1);
            }
        }

        // ensure K_{n+1} arrived before next S reads Ks
        CP_WAIT0;
        __syncthreads();   // bar3: K_{n+1} visible; Vs free

        // async-stage V_{n+1} into Vs (arrives during next S + softmax)
        if (pre) {
            const float* vt = vg + (size_t)(n+1) * 64 * D_;
            #pragma unroll
            for (int it = 0; it < 8; ++it)
                cpa16(saddr(Vs + (it*8 + lm)*136 + lc4*4),
                      vt + (it*8 + lm)*128 + lc4*4);
            CP_COMMIT;
        }
    }

    // final normalization: pass l across layouts via smem
    __syncthreads();
    if (c == 0) { red[wbase + g] = l0; red[wbase + g + 8] = l1; }
    __syncthreads();
    float inv0 = 1.f / red[wm2*32      + g], inv1 = 1.f / red[wm2*32      + g + 8];
    float inv2 = 1.f / red[wm2*32 + 16 + g], inv3 = 1.f / red[wm2*32 + 16 + g + 8];

    // outputs tf32-rounded so proj can raw-copy them
    const int bb = bh >> 3, hh = bh & 7;
    #pragma unroll
    for (int mt = 0; mt < 2; ++mt) {
        float iv0 = (mt == 0) ? inv0 : inv2;
        float iv1 = (mt == 0) ? inv1 : inv3;
        int t0 = qbase + wm2*32 + mt*16 + g;
        #pragma unroll
        for (int nt = 0; nt < 8; ++nt) {
            int d = wn2*64 + nt*8 + 2*c;
            float* p0 = g_ao + ((size_t)(bb*T_ + t0))*(H_*D_) + hh*128 + d;
            *(float2*)p0 = make_float2(__uint_as_float(f2tf(oacc[mt][nt].x * iv0)),
                                       __uint_as_float(f2tf(oacc[mt][nt].y * iv0)));
            float* p1 = g_ao + ((size_t)(bb*T_ + t0 + 8))*(H_*D_) + hh*128 + d;
            *(float2*)p1 = make_float2(__uint_as_float(f2tf(oacc[mt][nt].z * iv1)),
                                       __uint_as_float(f2tf(oacc[mt][nt].w * iv1)));
        }
    }
}

// ---------------------------------------------------------------------------
// Kernel 3: output projection, tf32 MMA, register double-buffered k-chunks.
// g_ao[8192,1024] @ g_wu[1024,128] + bu.  grid (128), 256 threads.
// Inputs pre-rounded -> raw bit stores, no cvt.
// ---------------------------------------------------------------------------
__global__ __launch_bounds__(256, 1)
void proj_kernel(const float* __restrict__ bu, float* __restrict__ out)
{
    extern __shared__ unsigned smu[];
    unsigned* As = smu;           // [64][68]
    unsigned* Bs = smu + 64*68;   // [64][136]

    const int by  = blockIdx.x;
    const int tid = threadIdx.x;
    const int wid = tid >> 5, lane = tid & 31;
    const int g = lane >> 2, c = lane & 3;
    const int wm = wid >> 1, wn = wid & 1;

    float4 acc[8];
    #pragma unroll
    for (int j = 0; j < 8; ++j) acc[j] = make_float4(0.f, 0.f, 0.f, 0.f);

    float4 areg[4], breg[8];
    // prologue: chunk 0
    #pragma unroll
    for (int it = 0; it < 4; ++it) {
        int lin = it * 256 + tid;
        int m = lin >> 4, c4 = lin & 15;
        areg[it] = *(const float4*)(g_ao + (size_t)(by*64 + m)*1024 + c4*4);
    }
    #pragma unroll
    for (int it = 0; it < 8; ++it) {
        int lin = it * 256 + tid;
        int k = lin >> 5, n4 = lin & 31;
        breg[it] = *(const float4*)(g_wu + (size_t)k*128 + n4*4);
    }

    for (int kc = 0; kc < 16; ++kc) {
        __syncthreads();   // previous compute done reading smem
        #pragma unroll
        for (int it = 0; it < 4; ++it) {
            int lin = it * 256 + tid;
            int m = lin >> 4, c4 = lin & 15;
            *(uint4*)(As + m*68 + c4*4) = f4bits(areg[it]);
        }
        #pragma unroll
        for (int it = 0; it < 8; ++it) {
            int lin = it * 256 + tid;
            int k = lin >> 5, n4 = lin & 31;
            *(uint4*)(Bs + k*136 + n4*4) = f4bits(breg[it]);
        }
        __syncthreads();

        // prefetch next chunk (latency hidden under compute)
        if (kc < 15) {
            #pragma unroll
            for (int it = 0; it < 4; ++it) {
                int lin = it * 256 + tid;
                int m = lin >> 4, c4 = lin & 15;
                areg[it] = *(const float4*)(g_ao + (size_t)(by*64 + m)*1024
                                                 + (kc+1)*64 + c4*4);
            }
            #pragma unroll
            for (int it = 0; it < 8; ++it) {
                int lin = it * 256 + tid;
                int k = lin >> 5, n4 = lin & 31;
                breg[it] = *(const float4*)(g_wu + (size_t)((kc+1)*64 + k)*128 + n4*4);
            }
        }

        #pragma unroll
        for (int k8 = 0; k8 < 8; ++k8) {
            int kk = k8 * 8;
            int r = wm*16 + g;
            unsigned a0 = As[r*68 + kk + c];
            unsigned a1 = As[(r+8)*68 + kk + c];
            unsigned a2 = As[r*68 + kk + c + 4];
            unsigned a3 = As[(r+8)*68 + kk + c + 4];
            #pragma unroll
            for (int nt = 0; nt < 8; ++nt) {
                unsigned b0 = Bs[(kk+c  )*136 + wn*64 + nt*8 + g];
                unsigned b1 = Bs[(kk+c+4)*136 + wn*64 + nt*8 + g];
                mma8(acc[nt], a0, a1, a2, a3, b0, b1);
            }
        }
    }

    #pragma unroll
    for (int nt = 0; nt < 8; ++nt) {
        int d = wn*64 + nt*8 + 2*c;
        float bv0 = bu[d], bv1 = bu[d + 1];
        int m0 = by*64 + wm*16 + g;
        *(float2*)(out + (size_t)m0*128 + d) =
            make_float2(acc[nt].x + bv0, acc[nt].y + bv1);
        *(float2*)(out + (size_t)(m0 + 8)*128 + d) =
            make_float2(acc[nt].z + bv0, acc[nt].w + bv1);
    }
}

// ---------------------------------------------------------------------------
extern "C" void kernel_launch(void* const* d_in, const int* in_sizes, int n_in,
                              void* d_out, int out_size)
{
    const float* x  = (const float*)d_in[0];
    const float* Wq = (const float*)d_in[1];
    const float* Wk = (const float*)d_in[2];
    const float* Wv = (const float*)d_in[3];
    const float* Wu = (const float*)d_in[4];
    const float* bu = (const float*)d_in[5];
    float* out = (float*)d_out;

    const int SMEM1 = (128*132 + 128*72) * (int)sizeof(unsigned);                  // 104448
    const int SMEM2 = (128*132 + 64*132 + 64*136 + 128*68 + 128) * (int)sizeof(unsigned); // 171520
    const int SMEM3 = (64*68 + 64*136) * (int)sizeof(unsigned);                    // 52224

    cudaFuncSetAttribute(qkv_kernel,  cudaFuncAttributeMaxDynamicSharedMemorySize, SMEM1);
    cudaFuncSetAttribute(attn_kernel, cudaFuncAttributeMaxDynamicSharedMemorySize, SMEM2);
    cudaFuncSetAttribute(proj_kernel, cudaFuncAttributeMaxDynamicSharedMemorySize, SMEM3);

    prep_kernel<<<dim3(128, 5), 256>>>(x, Wq, Wk, Wv, Wu);
    qkv_kernel<<<dim3(16, 64, 3), 256, SMEM1>>>();
    attn_kernel<<<dim3(16, 32), 256, SMEM2>>>();
    proj_kernel<<<dim3(128), 256, SMEM3>>>(bu, out);
}